// round 13
// baseline (speedup 1.0000x reference)
#include <cuda_runtime.h>
#include <cuda_bf16.h>
#include <math.h>
#include <stdint.h>

#define NF 96
#define GD 12
#define K2T 9
#define BN 4
#define HH 128
#define WW 128
#define HWSZ (HH*WW)

__device__ float g_t1[BN*NF*HWSZ];
__device__ float g_t2[BN*NF*HWSZ];
__device__ float g_e1[BN*NF*64*64];
__device__ float g_d1[BN*NF*64*64];
__device__ float g_off[BN*2*GD*K2T*HWSZ];
__device__ float g_S[BN*NF*K2T*HWSZ];

// ---------------- fp32 pipelined 3x3 s1 conv (oc1, oc3 — quantizer-exact) ----
__global__ __launch_bounds__(256) void conv3x3_s1v2(
    const float* __restrict__ inA, int cinA,
    const float* __restrict__ inB, int cinB,
    const float* __restrict__ w, const float* __restrict__ bias,
    float* __restrict__ out, int cout, int flags)
{
    const int tid = threadIdx.x;
    const int tx = tid & 15, ty = tid >> 4;
    const int x0 = (blockIdx.x & 1) * 64, y0 = (blockIdx.x >> 1) * 16;
    const int ocb = blockIdx.y * 8, n = blockIdx.z;
    const int cin = cinA + cinB, nch = cin >> 2;
    __shared__ float sIn[2][4][18][68];
    __shared__ float sW[2][8*4*9];
    float rI[19]; float rw0, rw1;

#define S1_LOAD(IC0) { const int ic0_=(IC0); \
    _Pragma("unroll") for (int k=0;k<19;k++){ int idx=tid+256*k; \
      if (k<18||tid<144){ int ic=idx/1188; int rem=idx-ic*1188; int rr=rem/66; int cc=rem-rr*66; \
        int gy=y0-1+rr, gx=x0-1+cc; bool inb=((unsigned)gy<(unsigned)HH)&&((unsigned)gx<(unsigned)WW); \
        int icg=ic0_+ic; const float* p=(icg<cinA)?(inA+((size_t)(n*cinA+icg)*HH+gy)*WW+gx):(inB+((size_t)(n*cinB+(icg-cinA))*HH+gy)*WW+gx); \
        rI[k]=inb?__ldg(p):0.f; } } \
    { int o=tid/36, ic=(tid/9)%4, t=tid%9; rw0=w[((size_t)(ocb+o)*cin+ic0_+ic)*9+t]; \
      if (tid<32){ int idx=tid+256; int o2=idx/36, ic2=(idx/9)%4, t2=idx%9; rw1=w[((size_t)(ocb+o2)*cin+ic0_+ic2)*9+t2]; } } }
#define S1_STORE(B) { float* sb=&sIn[B][0][0][0]; \
    _Pragma("unroll") for (int k=0;k<19;k++){ int idx=tid+256*k; \
      if (k<18||tid<144){ int ic=idx/1188; int rem=idx-ic*1188; int rr=rem/66; int cc=rem-rr*66; \
        sb[(ic*18+rr)*68+cc]=rI[k]; } } \
    sW[B][tid]=rw0; if (tid<32) sW[B][tid+256]=rw1; }

    float acc[8][4];
#pragma unroll
    for (int o=0;o<8;o++)
#pragma unroll
      for (int j=0;j<4;j++) acc[o][j]=0.f;
    S1_LOAD(0); S1_STORE(0); __syncthreads();
    for (int c=0;c<nch;c++){
        const int b=c&1;
        if (c+1<nch) S1_LOAD((c+1)*4);
#pragma unroll
        for (int ic=0;ic<4;ic++){
#pragma unroll
            for (int dy=0;dy<3;dy++){
                const float* rp=&sIn[b][ic][ty+dy][4*tx];
                float4 va=*(const float4*)rp; float2 vb=*(const float2*)(rp+4);
                float v[6]={va.x,va.y,va.z,va.w,vb.x,vb.y};
                const float* wrow=&sW[b][ic*9+dy*3];
#pragma unroll
                for (int dx=0;dx<3;dx++){
                    float wv[8];
#pragma unroll
                    for (int o=0;o<8;o++) wv[o]=wrow[o*36+dx];
#pragma unroll
                    for (int j=0;j<4;j++){ float xv=v[j+dx];
#pragma unroll
                        for (int o=0;o<8;o++) acc[o][j]=fmaf(wv[o],xv,acc[o][j]); }
                }
            }
        }
        if (c+1<nch){ S1_STORE((c+1)&1); __syncthreads(); }
    }
    const int y=y0+ty, xb=x0+4*tx;
#pragma unroll
    for (int o=0;o<8;o++){
        float bv=bias[ocb+o];
        float v0=acc[o][0]+bv,v1=acc[o][1]+bv,v2=acc[o][2]+bv,v3=acc[o][3]+bv;
        if (flags&1){ v0=(v0>=0.f)?v0:0.1f*v0; v1=(v1>=0.f)?v1:0.1f*v1; v2=(v2>=0.f)?v2:0.1f*v2; v3=(v3>=0.f)?v3:0.1f*v3; }
        float* op=out+((size_t)(n*cout+ocb+o)*HH+y)*WW+xb;
        if (flags&2){ float4 p=*(float4*)op; p.x+=v0;p.y+=v1;p.z+=v2;p.w+=v3; *(float4*)op=p; }
        else *(float4*)op=make_float4(v0,v1,v2,v3);
    }
#undef S1_LOAD
#undef S1_STORE
}

// ---------------- fp32 pipelined 3x3 s2 conv (e1, e2) ------------------------
__global__ __launch_bounds__(256) void conv3x3_s2v2(
    const float* __restrict__ in, int Hin,
    const float* __restrict__ w, const float* __restrict__ bias,
    float* __restrict__ out, float* __restrict__ out_q, int flags)
{
    const int tid=threadIdx.x, tx=tid&15, ty=tid>>4;
    const int Hout=Hin>>1, tilesX=Hout>>4;
    const int x0=(blockIdx.x%tilesX)*16, y0=(blockIdx.x/tilesX)*16;
    const int ocb=blockIdx.y*8, n=blockIdx.z;
    __shared__ float sIn[2][2][33][34];
    __shared__ float sW[2][8*2*9];
    float rI[9]; float rw0;
#define S2_LOAD(IC0) { const int ic0_=(IC0); \
    _Pragma("unroll") for (int k=0;k<9;k++){ int idx=tid+256*k; \
      if (k<8||tid<130){ int ic=idx/1089; int rem=idx-ic*1089; int rr=rem/33; int cc=rem-rr*33; \
        int gy=2*y0+rr, gx=2*x0+cc; bool inb=(gy<Hin)&&(gx<Hin); \
        rI[k]=inb?__ldg(in+((size_t)(n*NF+ic0_+ic)*Hin+gy)*Hin+gx):0.f; } } \
    if (tid<144){ int o=tid/18, ic=(tid/9)%2, t=tid%9; rw0=w[((size_t)(ocb+o)*NF+ic0_+ic)*9+t]; } }
#define S2_STORE(B) { float* sb=&sIn[B][0][0][0]; \
    _Pragma("unroll") for (int k=0;k<9;k++){ int idx=tid+256*k; \
      if (k<8||tid<130){ int ic=idx/1089; int rem=idx-ic*1089; int rr=rem/33; int cc=rem-rr*33; \
        sb[(ic*33+rr)*34+cc]=rI[k]; } } \
    if (tid<144) sW[B][tid]=rw0; }
    float acc[8];
#pragma unroll
    for (int o=0;o<8;o++) acc[o]=0.f;
    S2_LOAD(0); S2_STORE(0); __syncthreads();
    const int nch=NF/2;
    for (int c=0;c<nch;c++){
        const int b=c&1;
        if (c+1<nch) S2_LOAD((c+1)*2);
#pragma unroll
        for (int ic=0;ic<2;ic++)
#pragma unroll
            for (int dy=0;dy<3;dy++)
#pragma unroll
                for (int dx=0;dx<3;dx++){
                    float xv=sIn[b][ic][2*ty+dy][2*tx+dx];
                    const float* wp=&sW[b][ic*9+dy*3+dx];
#pragma unroll
                    for (int o=0;o<8;o++) acc[o]=fmaf(wp[o*18],xv,acc[o]);
                }
        if (c+1<nch){ S2_STORE((c+1)&1); __syncthreads(); }
    }
#pragma unroll
    for (int o=0;o<8;o++){
        float v=acc[o]+bias[ocb+o];
        if (flags&1) v=(v>=0.f)?v:0.1f*v;
        size_t oi=((size_t)(n*NF+ocb+o)*Hout+(y0+ty))*Hout+(x0+tx);
        out[oi]=v;
        if (out_q) out_q[oi]=rintf(v);
    }
#undef S2_LOAD
#undef S2_STORE
}

// ---------------- fp32 transpose conv (d1, d2) --------------------------------
__global__ __launch_bounds__(256) void deconv3x3_x2(
    const float* __restrict__ in, int Hin,
    const float* __restrict__ w, const float* __restrict__ bias,
    float* __restrict__ out, int flags)
{
    const int tid=threadIdx.x, tx=tid&15, ty=tid>>4;
    const int Hout=Hin*2, tilesX=Hout>>5;
    const int tX=blockIdx.x%tilesX, tY=blockIdx.x/tilesX;
    const int xin0=tX*16, yin0=tY*16, x0o=tX*32, y0o=tY*32;
    const int ocb=blockIdx.y*8, n=blockIdx.z;
    __shared__ float sIn[4][17][18];
    __shared__ float sW[8][4][9];
    float aEE[8],aEO[8],aOE[8],aOO[8];
#pragma unroll
    for (int o=0;o<8;o++){aEE[o]=0.f;aEO[o]=0.f;aOE[o]=0.f;aOO[o]=0.f;}
    for (int ic0=0;ic0<NF;ic0+=4){
        __syncthreads();
        for (int idx=tid;idx<4*17*17;idx+=256){
            int ic=idx/(17*17), r=(idx/17)%17, c=idx%17;
            int gy=yin0-1+r, gx=xin0-1+c;
            float v=0.f;
            if ((unsigned)gy<(unsigned)Hin&&(unsigned)gx<(unsigned)Hin)
                v=in[((size_t)(n*NF+ic0+ic)*Hin+gy)*Hin+gx];
            sIn[ic][r][c]=v;
        }
        for (int idx=tid;idx<8*4*9;idx+=256){
            int o=idx/36, ic=(idx/9)%4, t=idx%9;
            sW[o][ic][t]=w[((size_t)(ocb+o)*NF+ic0+ic)*9+t];
        }
        __syncthreads();
#pragma unroll
        for (int ic=0;ic<4;ic++){
            float v00=sIn[ic][ty][tx], v01=sIn[ic][ty][tx+1];
            float v10=sIn[ic][ty+1][tx], v11=sIn[ic][ty+1][tx+1];
#pragma unroll
            for (int o=0;o<8;o++){
                const float* wp=&sW[o][ic][0];
                aEE[o]=fmaf(wp[0],v00,aEE[o]); aEE[o]=fmaf(wp[2],v01,aEE[o]);
                aEE[o]=fmaf(wp[6],v10,aEE[o]); aEE[o]=fmaf(wp[8],v11,aEE[o]);
                aEO[o]=fmaf(wp[1],v01,aEO[o]); aEO[o]=fmaf(wp[7],v11,aEO[o]);
                aOE[o]=fmaf(wp[3],v10,aOE[o]); aOE[o]=fmaf(wp[5],v11,aOE[o]);
                aOO[o]=fmaf(wp[4],v11,aOO[o]);
            }
        }
    }
    const int ye=y0o+2*ty, xe=x0o+2*tx;
#pragma unroll
    for (int o=0;o<8;o++){
        float bv=bias[ocb+o];
        float vEE=aEE[o]+bv,vEO=aEO[o]+bv,vOE=aOE[o]+bv,vOO=aOO[o]+bv;
        if (flags&1){ vEE=(vEE>=0.f)?vEE:0.1f*vEE; vEO=(vEO>=0.f)?vEO:0.1f*vEO;
                      vOE=(vOE>=0.f)?vOE:0.1f*vOE; vOO=(vOO>=0.f)?vOO:0.1f*vOO; }
        size_t base=((size_t)(n*NF+ocb+o)*Hout+ye)*Hout+xe;
        out[base]=vEE; out[base+1]=vEO; out[base+Hout]=vOE; out[base+Hout+1]=vOO;
    }
}

// ---------------- DCN sampling ------------------------------------------------
__global__ __launch_bounds__(256) void dcn_sample(
    const float* __restrict__ ref, const float* __restrict__ off,
    float* __restrict__ S)
{
    int idx=blockIdx.x*256+threadIdx.x;
    if (idx>=BN*GD*K2T*HWSZ) return;
    int p=idx&(HWSZ-1); int t=idx>>14;
    int k=t%9; t/=9; int g=t%GD, n=t/GD;
    int y=p>>7, x=p&127;
    int offc=(g*9+k)*2;
    float dy=off[((size_t)(n*2*GD*K2T+offc))*HWSZ+p];
    float dx=off[((size_t)(n*2*GD*K2T+offc+1))*HWSZ+p];
    float py=(float)y+(float)(k/3-1)+dy;
    float px=(float)x+(float)(k%3-1)+dx;
    float fy=floorf(py), fx=floorf(px);
    float wy=py-fy, wx=px-fx;
    int iy=(int)fy, ix=(int)fx;
    float wgt[4]; int ofs[4];
#pragma unroll
    for (int r=0;r<2;r++)
#pragma unroll
        for (int c=0;c<2;c++){
            int yy=iy+r, xx=ix+c;
            bool val=((unsigned)yy<(unsigned)HH)&&((unsigned)xx<(unsigned)WW);
            float wv=(r?wy:1.f-wy)*(c?wx:1.f-wx);
            wgt[r*2+c]=val?wv:0.f; ofs[r*2+c]=val?(yy*WW+xx):0;
        }
    const float* base=ref+(size_t)(n*NF+g*8)*HWSZ;
    float* so=S+((size_t)(n*NF+g*8)*9+k)*HWSZ+p;
#pragma unroll
    for (int c=0;c<8;c++){
        const float* bp=base+(size_t)c*HWSZ;
        so[(size_t)c*9*HWSZ]=wgt[0]*bp[ofs[0]]+wgt[1]*bp[ofs[1]]+wgt[2]*bp[ofs[2]]+wgt[3]*bp[ofs[3]];
    }
}

// ================= mma.sync bf16 split-3 GEMM (decode-table G_LOAD) ==========
__device__ __forceinline__ void split2(float v0, float v1, uint32_t& hi, uint32_t& lo){
    __nv_bfloat16 h0=__float2bfloat16(v0), h1=__float2bfloat16(v1);
    __nv_bfloat16 l0=__float2bfloat16(v0-__bfloat162float(h0));
    __nv_bfloat16 l1=__float2bfloat16(v1-__bfloat162float(h1));
    hi=((uint32_t)__bfloat16_as_ushort(h1)<<16)|__bfloat16_as_ushort(h0);
    lo=((uint32_t)__bfloat16_as_ushort(l1)<<16)|__bfloat16_as_ushort(l0);
}
#define MMA4(d,a0,a1,a2,a3,b0,b1) \
    asm volatile("mma.sync.aligned.m16n8k16.row.col.f32.bf16.bf16.f32 " \
        "{%0,%1,%2,%3},{%4,%5,%6,%7},{%8,%9},{%0,%1,%2,%3};" \
        : "+f"(d[0]),"+f"(d[1]),"+f"(d[2]),"+f"(d[3]) \
        : "r"(a[0]),"r"(a[1]),"r"(a[2]),"r"(a[3]),"r"(b0),"r"(b1))
#define LDSM4(r0,r1,r2,r3,a) \
    asm volatile("ldmatrix.sync.aligned.m8n8.x4.shared.b16 {%0,%1,%2,%3},[%4];" \
        : "=r"(r0),"=r"(r1),"=r"(r2),"=r"(r3) : "r"(a))
#define LDSM2(r0,r1,a) \
    asm volatile("ldmatrix.sync.aligned.m8n8.x2.shared.b16 {%0,%1},[%2];" \
        : "=r"(r0),"=r"(r1) : "r"(a))
__device__ __forceinline__ void mma4b(float* d, const uint32_t* a, uint32_t b0, uint32_t b1){
    asm volatile("mma.sync.aligned.m16n8k16.row.col.f32.bf16.bf16.f32 "
        "{%0,%1,%2,%3},{%4,%5,%6,%7},{%8,%9},{%0,%1,%2,%3};"
        : "+f"(d[0]),"+f"(d[1]),"+f"(d[2]),"+f"(d[3])
        : "r"(a[0]),"r"(a[1]),"r"(a[2]),"r"(a[3]),"r"(b0),"r"(b1));
}

template<int NF8, int MODE>
__global__ __launch_bounds__(256) void gemm_tc(
    const float* __restrict__ inA, int cinA,
    const float* __restrict__ inB, int cinB,
    const float* __restrict__ w, const float* __restrict__ bias,
    float* __restrict__ out, int cout, int flags)
{
    extern __shared__ uint32_t sm[];
    const int Ncta = NF8*16;
    const int AW = 128*20, BW = Ncta*20, PB = 2*AW + 2*BW;
    const int tid=threadIdx.x, lane=tid&31, wid=tid>>5;
    const int g=lane>>2, tig=lane&3;
    const int y=blockIdx.x, n=blockIdx.z;
    const int ocb = blockIdx.y * Ncta;
    const int cin = cinA + cinB;
    const int K = MODE ? cin : cin*9;
    const int nch = K/32;
    const int mIdx = (wid&3)*32, nIdx = (wid>>2)*NF8*8;
    const int apx = tid & 127, ah_ = tid >> 7;

    const uint32_t smb = (uint32_t)__cvta_generic_to_shared(sm);
    const uint32_t PB4 = PB*4, AW4 = AW*4, BW4 = BW*4;
    const uint32_t rowA = (uint32_t)((mIdx + (lane&15))*80) + ((lane&16)?16u:0u);
    const uint32_t rowB = (uint32_t)((nIdx + (lane&7))*80) + ((lane&8)?16u:0u);

    // k-pair decode table: packed (ic0,dy0,dx0 | ic1,dy1,dx1); built once.
    uint32_t* stab = sm + 2*PB;
    if (!MODE){
        for (int k2 = tid; k2 < (K>>1); k2 += 256){
            int k0=k2*2, k1=k0+1;
            int ic0=k0/9, t0=k0-ic0*9;
            int ic1=k1/9, t1=k1-ic1*9;
            stab[k2] = (uint32_t)ic0 | ((uint32_t)(t0/3)<<11) | ((uint32_t)(t0%3)<<13)
                     | ((uint32_t)ic1<<16) | ((uint32_t)(t1/3)<<27) | ((uint32_t)(t1%3)<<29);
        }
        __syncthreads();
    }

    uint32_t pah[8], pal[8], pbh[NF8], pbl[NF8];

#define G_LOAD(C) { const int c_=(C); \
    if (MODE){ \
        _Pragma("unroll") for (int i=0;i<8;i++){ \
            int k0 = c_*32 + (ah_*8+i)*2; \
            float v0 = __ldg(inA + ((size_t)(n*cin + k0  ))*HWSZ + y*WW + apx); \
            float v1 = __ldg(inA + ((size_t)(n*cin + k0+1))*HWSZ + y*WW + apx); \
            split2(v0, v1, pah[i], pal[i]); } \
        _Pragma("unroll") for (int j=0;j<NF8;j++){ \
            int idx = tid + 256*j; int oc = idx>>4, kp = idx&15; \
            int k0 = c_*32 + kp*2; int ocg = ocb + oc; \
            float v0=0.f, v1=0.f; \
            if (ocg < cout){ v0=__ldg(w+(size_t)ocg*cin+k0); v1=__ldg(w+(size_t)ocg*cin+k0+1); } \
            split2(v0, v1, pbh[j], pbl[j]); } \
    } else { \
        _Pragma("unroll") for (int i=0;i<8;i++){ \
            int k0 = c_*32 + (ah_*8+i)*2; \
            uint32_t e = stab[k0>>1]; \
            int ic0=e&2047, dy0=(e>>11)&3, dx0=(e>>13)&3; \
            int ic1=(e>>16)&2047, dy1=(e>>27)&3, dx1=(e>>29)&3; \
            float v0=0.f, v1=0.f; \
            { int gy=y-1+dy0, gx=apx-1+dx0; \
              if ((unsigned)gy<128u && (unsigned)gx<128u){ \
                const float* pl=(ic0<cinA)? inA+((size_t)(n*cinA+ic0))*HWSZ \
                                          : inB+((size_t)(n*cinB+ic0-cinA))*HWSZ; \
                v0=__ldg(pl+gy*WW+gx); } } \
            { int gy=y-1+dy1, gx=apx-1+dx1; \
              if ((unsigned)gy<128u && (unsigned)gx<128u){ \
                const float* pl=(ic1<cinA)? inA+((size_t)(n*cinA+ic1))*HWSZ \
                                          : inB+((size_t)(n*cinB+ic1-cinA))*HWSZ; \
                v1=__ldg(pl+gy*WW+gx); } } \
            split2(v0, v1, pah[i], pal[i]); } \
        _Pragma("unroll") for (int j=0;j<NF8;j++){ \
            int idx = tid + 256*j; int oc = idx>>4, kp = idx&15; \
            int k0 = c_*32 + kp*2; int ocg = ocb + oc; \
            uint32_t e = stab[k0>>1]; \
            int ic0=e&2047, t0=((e>>11)&3)*3+((e>>13)&3); \
            int ic1=(e>>16)&2047, t1=((e>>27)&3)*3+((e>>29)&3); \
            float v0=0.f, v1=0.f; \
            if (ocg < cout){ \
                v0=__ldg(w+((size_t)ocg*cin+ic0)*9+t0); \
                v1=__ldg(w+((size_t)ocg*cin+ic1)*9+t1); } \
            split2(v0, v1, pbh[j], pbl[j]); } \
    } }

#define G_STORE(B) { uint32_t* bb = sm + (B)*PB; \
    _Pragma("unroll") for (int i=0;i<8;i++){ \
        int word = apx*20 + ah_*8 + i; \
        bb[word] = pah[i]; bb[AW + word] = pal[i]; } \
    _Pragma("unroll") for (int j=0;j<NF8;j++){ \
        int idx = tid + 256*j; int oc = idx>>4, kp = idx&15; \
        int word = oc*20 + kp; \
        bb[2*AW + word] = pbh[j]; bb[2*AW + BW + word] = pbl[j]; } }

    float acc[2][NF8][4];
#pragma unroll
    for (int mt=0;mt<2;mt++)
#pragma unroll
        for (int j=0;j<NF8;j++)
#pragma unroll
            for (int q=0;q<4;q++) acc[mt][j][q]=0.f;

    G_LOAD(0); G_STORE(0); __syncthreads();

    for (int c=0;c<nch;c++){
        const int b=c&1;
        if (c+1<nch) G_LOAD(c+1);
        const uint32_t base = smb + b*PB4;
#pragma unroll
        for (int ks=0;ks<2;ks++){
            const uint32_t aoff = base + (uint32_t)(ks*32) + rowA;
            uint32_t ha[2][4], la[2][4];
#pragma unroll
            for (int mt=0;mt<2;mt++){
                LDSM4(ha[mt][0],ha[mt][1],ha[mt][2],ha[mt][3], aoff + mt*1280u);
                LDSM4(la[mt][0],la[mt][1],la[mt][2],la[mt][3], aoff + AW4 + mt*1280u);
            }
            const uint32_t boff0 = base + 2u*AW4 + (uint32_t)(ks*32) + rowB;
#pragma unroll
            for (int j=0;j<NF8;j++){
                uint32_t bh0,bh1,bl0,bl1;
                const uint32_t boff = boff0 + j*640u;
                LDSM2(bh0,bh1, boff);
                LDSM2(bl0,bl1, boff + BW4);
#pragma unroll
                for (int mt=0;mt<2;mt++){
                    mma4b(acc[mt][j], ha[mt], bh0,bh1);
                    mma4b(acc[mt][j], la[mt], bh0,bh1);
                    mma4b(acc[mt][j], ha[mt], bl0,bl1);
                }
            }
        }
        if (c+1<nch){ G_STORE((c+1)&1); __syncthreads(); }
    }

#pragma unroll
    for (int mt=0;mt<2;mt++){
        int px0 = mIdx + mt*16 + g;
#pragma unroll
        for (int j=0;j<NF8;j++){
            int oc0 = ocb + nIdx + j*8 + 2*tig;
#pragma unroll
            for (int q=0;q<4;q++){
                int oc = oc0 + (q&1);
                int px = px0 + ((q>>1)*8);
                if (oc < cout){
                    float v = acc[mt][j][q] + bias[oc];
                    if (flags&1) v=(v>=0.f)?v:0.1f*v;
                    float* op = out + ((size_t)(n*cout+oc)*HH + y)*WW + px;
                    if (flags&2) *op += v; else *op = v;
                }
            }
        }
    }
#undef G_LOAD
#undef G_STORE
}

// ------------------------------ launch ---------------------------------------
extern "C" void kernel_launch(void* const* d_in, const int* in_sizes, int n_in,
                              void* d_out, int out_size)
{
    const float* ref   = (const float*)d_in[0];
    const float* inp   = (const float*)d_in[1];
    const float* w_oc1 = (const float*)d_in[2];  const float* b_oc1 = (const float*)d_in[3];
    const float* w_oc3 = (const float*)d_in[4];  const float* b_oc3 = (const float*)d_in[5];
    const float* w_e1  = (const float*)d_in[6];  const float* b_e1  = (const float*)d_in[7];
    const float* w_e2  = (const float*)d_in[8];  const float* b_e2  = (const float*)d_in[9];
    const float* w_d1  = (const float*)d_in[10]; const float* b_d1  = (const float*)d_in[11];
    const float* w_d2  = (const float*)d_in[12]; const float* b_d2  = (const float*)d_in[13];
    const float* w_off = (const float*)d_in[14]; const float* b_off = (const float*)d_in[15];
    const float* w_dcn = (const float*)d_in[16]; const float* b_dcn = (const float*)d_in[17];
    const float* w_c1  = (const float*)d_in[18]; const float* b_c1  = (const float*)d_in[19];
    const float* w_c2  = (const float*)d_in[20]; const float* b_c2  = (const float*)d_in[21];

    float* out  = (float*)d_out;
    float* oL1  = out;
    float* oEN  = out + (size_t)BN*NF*HWSZ;
    float* oQ   = oEN + (size_t)BN*NF*32*32;
    float* oDEC = oQ  + (size_t)BN*NF*32*32;

    float *t1, *t2, *e1b, *d1b, *offb, *Sb;
    cudaGetSymbolAddress((void**)&t1,   g_t1);
    cudaGetSymbolAddress((void**)&t2,   g_t2);
    cudaGetSymbolAddress((void**)&e1b,  g_e1);
    cudaGetSymbolAddress((void**)&d1b,  g_d1);
    cudaGetSymbolAddress((void**)&offb, g_off);
    cudaGetSymbolAddress((void**)&Sb,   g_S);

    // dyn smem: 2 tile buffers + 896-entry decode table
    const int smem7 = (2*(2*128*20 + 2*112*20))*4 + 896*4;   // 80384
    const int smem6 = (2*(2*128*20 + 2*96*20))*4 + 896*4;    // 75264
    cudaFuncSetAttribute(gemm_tc<7,0>, cudaFuncAttributeMaxDynamicSharedMemorySize, smem7);
    cudaFuncSetAttribute(gemm_tc<6,0>, cudaFuncAttributeMaxDynamicSharedMemorySize, smem6);
    cudaFuncSetAttribute(gemm_tc<6,1>, cudaFuncAttributeMaxDynamicSharedMemorySize, smem6);

    // oc1/oc3: bit-exact fp32 (feeds the quantizer — proven safe)
    conv3x3_s1v2<<<dim3(16, 12, BN), 256>>>(ref, NF, inp, NF, w_oc1, b_oc1, t1, NF, 1);
    conv3x3_s1v2<<<dim3(16, 12, BN), 256>>>(t1, NF, nullptr, 0, w_oc3, b_oc3, t2, NF, 1);
    conv3x3_s2v2<<<dim3(16, 12, BN), 256>>>(t2, 128, w_e1, b_e1, e1b, nullptr, 1);
    conv3x3_s2v2<<<dim3(4,  12, BN), 256>>>(e1b, 64, w_e2, b_e2, oEN, oQ, 0);
    deconv3x3_x2<<<dim3(4,  12, BN), 256>>>(oQ,  32, w_d1, b_d1, d1b, 1);
    deconv3x3_x2<<<dim3(16, 12, BN), 256>>>(d1b, 64, w_d2, b_d2, oDEC, 0);
    // offset head (216 ch): 2 oc-blocks of 112
    gemm_tc<7,0><<<dim3(128, 2, BN), 256, smem7>>>(oDEC, NF, nullptr, 0, w_off, b_off, offb, 216, 0);
    dcn_sample<<<(BN*GD*K2T*HWSZ)/256, 256>>>(ref, offb, Sb);
    // DCN 1x1 GEMM over 864 channels
    gemm_tc<6,1><<<dim3(128, 1, BN), 256, smem6>>>(Sb, NF*K2T, nullptr, 0, w_dcn, b_dcn, oL1, NF, 0);
    // fusion tail
    gemm_tc<6,0><<<dim3(128, 1, BN), 256, smem6>>>(oL1, NF, ref, NF, w_c1, b_c1, t1, NF, 1);
    gemm_tc<6,0><<<dim3(128, 1, BN), 256, smem6>>>(t1, NF, nullptr, 0, w_c2, b_c2, oL1, NF, 3);
}

// round 14
// speedup vs baseline: 1.1890x; 1.1890x over previous
#include <cuda_runtime.h>
#include <cuda_bf16.h>
#include <math.h>
#include <stdint.h>

#define NF 96
#define GD 12
#define K2T 9
#define BN 4
#define HH 128
#define WW 128
#define HWSZ (HH*WW)

__device__ float g_t1[BN*NF*HWSZ];
__device__ float g_t2[BN*NF*HWSZ];
__device__ float g_e1[BN*NF*64*64];
__device__ float g_d1[BN*NF*64*64];
__device__ float g_off[BN*2*GD*K2T*HWSZ];
__device__ float g_S[BN*NF*K2T*HWSZ];

// ---------------- fp32 pipelined 3x3 s1 conv (oc1, oc3) ----------------------
__global__ __launch_bounds__(256) void conv3x3_s1v2(
    const float* __restrict__ inA, int cinA,
    const float* __restrict__ inB, int cinB,
    const float* __restrict__ w, const float* __restrict__ bias,
    float* __restrict__ out, int cout, int flags)
{
    const int tid = threadIdx.x;
    const int tx = tid & 15, ty = tid >> 4;
    const int x0 = (blockIdx.x & 1) * 64, y0 = (blockIdx.x >> 1) * 16;
    const int ocb = blockIdx.y * 8, n = blockIdx.z;
    const int cin = cinA + cinB, nch = cin >> 2;
    __shared__ float sIn[2][4][18][68];
    __shared__ float sW[2][8*4*9];
    float rI[19]; float rw0, rw1;

#define S1_LOAD(IC0) { const int ic0_=(IC0); \
    _Pragma("unroll") for (int k=0;k<19;k++){ int idx=tid+256*k; \
      if (k<18||tid<144){ int ic=idx/1188; int rem=idx-ic*1188; int rr=rem/66; int cc=rem-rr*66; \
        int gy=y0-1+rr, gx=x0-1+cc; bool inb=((unsigned)gy<(unsigned)HH)&&((unsigned)gx<(unsigned)WW); \
        int icg=ic0_+ic; const float* p=(icg<cinA)?(inA+((size_t)(n*cinA+icg)*HH+gy)*WW+gx):(inB+((size_t)(n*cinB+(icg-cinA))*HH+gy)*WW+gx); \
        rI[k]=inb?__ldg(p):0.f; } } \
    { int o=tid/36, ic=(tid/9)%4, t=tid%9; rw0=w[((size_t)(ocb+o)*cin+ic0_+ic)*9+t]; \
      if (tid<32){ int idx=tid+256; int o2=idx/36, ic2=(idx/9)%4, t2=idx%9; rw1=w[((size_t)(ocb+o2)*cin+ic0_+ic2)*9+t2]; } } }
#define S1_STORE(B) { float* sb=&sIn[B][0][0][0]; \
    _Pragma("unroll") for (int k=0;k<19;k++){ int idx=tid+256*k; \
      if (k<18||tid<144){ int ic=idx/1188; int rem=idx-ic*1188; int rr=rem/66; int cc=rem-rr*66; \
        sb[(ic*18+rr)*68+cc]=rI[k]; } } \
    sW[B][tid]=rw0; if (tid<32) sW[B][tid+256]=rw1; }

    float acc[8][4];
#pragma unroll
    for (int o=0;o<8;o++)
#pragma unroll
      for (int j=0;j<4;j++) acc[o][j]=0.f;
    S1_LOAD(0); S1_STORE(0); __syncthreads();
    for (int c=0;c<nch;c++){
        const int b=c&1;
        if (c+1<nch) S1_LOAD((c+1)*4);
#pragma unroll
        for (int ic=0;ic<4;ic++){
#pragma unroll
            for (int dy=0;dy<3;dy++){
                const float* rp=&sIn[b][ic][ty+dy][4*tx];
                float4 va=*(const float4*)rp; float2 vb=*(const float2*)(rp+4);
                float v[6]={va.x,va.y,va.z,va.w,vb.x,vb.y};
                const float* wrow=&sW[b][ic*9+dy*3];
#pragma unroll
                for (int dx=0;dx<3;dx++){
                    float wv[8];
#pragma unroll
                    for (int o=0;o<8;o++) wv[o]=wrow[o*36+dx];
#pragma unroll
                    for (int j=0;j<4;j++){ float xv=v[j+dx];
#pragma unroll
                        for (int o=0;o<8;o++) acc[o][j]=fmaf(wv[o],xv,acc[o][j]); }
                }
            }
        }
        if (c+1<nch){ S1_STORE((c+1)&1); __syncthreads(); }
    }
    const int y=y0+ty, xb=x0+4*tx;
#pragma unroll
    for (int o=0;o<8;o++){
        float bv=bias[ocb+o];
        float v0=acc[o][0]+bv,v1=acc[o][1]+bv,v2=acc[o][2]+bv,v3=acc[o][3]+bv;
        if (flags&1){ v0=(v0>=0.f)?v0:0.1f*v0; v1=(v1>=0.f)?v1:0.1f*v1; v2=(v2>=0.f)?v2:0.1f*v2; v3=(v3>=0.f)?v3:0.1f*v3; }
        float* op=out+((size_t)(n*cout+ocb+o)*HH+y)*WW+xb;
        if (flags&2){ float4 p=*(float4*)op; p.x+=v0;p.y+=v1;p.z+=v2;p.w+=v3; *(float4*)op=p; }
        else *(float4*)op=make_float4(v0,v1,v2,v3);
    }
#undef S1_LOAD
#undef S1_STORE
}

// ---------------- fp32 pipelined 3x3 s2 conv (e1, e2) ------------------------
__global__ __launch_bounds__(256) void conv3x3_s2v2(
    const float* __restrict__ in, int Hin,
    const float* __restrict__ w, const float* __restrict__ bias,
    float* __restrict__ out, float* __restrict__ out_q, int flags)
{
    const int tid=threadIdx.x, tx=tid&15, ty=tid>>4;
    const int Hout=Hin>>1, tilesX=Hout>>4;
    const int x0=(blockIdx.x%tilesX)*16, y0=(blockIdx.x/tilesX)*16;
    const int ocb=blockIdx.y*8, n=blockIdx.z;
    __shared__ float sIn[2][2][33][34];
    __shared__ float sW[2][8*2*9];
    float rI[9]; float rw0;
#define S2_LOAD(IC0) { const int ic0_=(IC0); \
    _Pragma("unroll") for (int k=0;k<9;k++){ int idx=tid+256*k; \
      if (k<8||tid<130){ int ic=idx/1089; int rem=idx-ic*1089; int rr=rem/33; int cc=rem-rr*33; \
        int gy=2*y0+rr, gx=2*x0+cc; bool inb=(gy<Hin)&&(gx<Hin); \
        rI[k]=inb?__ldg(in+((size_t)(n*NF+ic0_+ic)*Hin+gy)*Hin+gx):0.f; } } \
    if (tid<144){ int o=tid/18, ic=(tid/9)%2, t=tid%9; rw0=w[((size_t)(ocb+o)*NF+ic0_+ic)*9+t]; } }
#define S2_STORE(B) { float* sb=&sIn[B][0][0][0]; \
    _Pragma("unroll") for (int k=0;k<9;k++){ int idx=tid+256*k; \
      if (k<8||tid<130){ int ic=idx/1089; int rem=idx-ic*1089; int rr=rem/33; int cc=rem-rr*33; \
        sb[(ic*33+rr)*34+cc]=rI[k]; } } \
    if (tid<144) sW[B][tid]=rw0; }
    float acc[8];
#pragma unroll
    for (int o=0;o<8;o++) acc[o]=0.f;
    S2_LOAD(0); S2_STORE(0); __syncthreads();
    const int nch=NF/2;
    for (int c=0;c<nch;c++){
        const int b=c&1;
        if (c+1<nch) S2_LOAD((c+1)*2);
#pragma unroll
        for (int ic=0;ic<2;ic++)
#pragma unroll
            for (int dy=0;dy<3;dy++)
#pragma unroll
                for (int dx=0;dx<3;dx++){
                    float xv=sIn[b][ic][2*ty+dy][2*tx+dx];
                    const float* wp=&sW[b][ic*9+dy*3+dx];
#pragma unroll
                    for (int o=0;o<8;o++) acc[o]=fmaf(wp[o*18],xv,acc[o]);
                }
        if (c+1<nch){ S2_STORE((c+1)&1); __syncthreads(); }
    }
#pragma unroll
    for (int o=0;o<8;o++){
        float v=acc[o]+bias[ocb+o];
        if (flags&1) v=(v>=0.f)?v:0.1f*v;
        size_t oi=((size_t)(n*NF+ocb+o)*Hout+(y0+ty))*Hout+(x0+tx);
        out[oi]=v;
        if (out_q) out_q[oi]=rintf(v);
    }
#undef S2_LOAD
#undef S2_STORE
}

// ---------------- fp32 transpose conv (d1, d2) --------------------------------
__global__ __launch_bounds__(256) void deconv3x3_x2(
    const float* __restrict__ in, int Hin,
    const float* __restrict__ w, const float* __restrict__ bias,
    float* __restrict__ out, int flags)
{
    const int tid=threadIdx.x, tx=tid&15, ty=tid>>4;
    const int Hout=Hin*2, tilesX=Hout>>5;
    const int tX=blockIdx.x%tilesX, tY=blockIdx.x/tilesX;
    const int xin0=tX*16, yin0=tY*16, x0o=tX*32, y0o=tY*32;
    const int ocb=blockIdx.y*8, n=blockIdx.z;
    __shared__ float sIn[4][17][18];
    __shared__ float sW[8][4][9];
    float aEE[8],aEO[8],aOE[8],aOO[8];
#pragma unroll
    for (int o=0;o<8;o++){aEE[o]=0.f;aEO[o]=0.f;aOE[o]=0.f;aOO[o]=0.f;}
    for (int ic0=0;ic0<NF;ic0+=4){
        __syncthreads();
        for (int idx=tid;idx<4*17*17;idx+=256){
            int ic=idx/(17*17), r=(idx/17)%17, c=idx%17;
            int gy=yin0-1+r, gx=xin0-1+c;
            float v=0.f;
            if ((unsigned)gy<(unsigned)Hin&&(unsigned)gx<(unsigned)Hin)
                v=in[((size_t)(n*NF+ic0+ic)*Hin+gy)*Hin+gx];
            sIn[ic][r][c]=v;
        }
        for (int idx=tid;idx<8*4*9;idx+=256){
            int o=idx/36, ic=(idx/9)%4, t=idx%9;
            sW[o][ic][t]=w[((size_t)(ocb+o)*NF+ic0+ic)*9+t];
        }
        __syncthreads();
#pragma unroll
        for (int ic=0;ic<4;ic++){
            float v00=sIn[ic][ty][tx], v01=sIn[ic][ty][tx+1];
            float v10=sIn[ic][ty+1][tx], v11=sIn[ic][ty+1][tx+1];
#pragma unroll
            for (int o=0;o<8;o++){
                const float* wp=&sW[o][ic][0];
                aEE[o]=fmaf(wp[0],v00,aEE[o]); aEE[o]=fmaf(wp[2],v01,aEE[o]);
                aEE[o]=fmaf(wp[6],v10,aEE[o]); aEE[o]=fmaf(wp[8],v11,aEE[o]);
                aEO[o]=fmaf(wp[1],v01,aEO[o]); aEO[o]=fmaf(wp[7],v11,aEO[o]);
                aOE[o]=fmaf(wp[3],v10,aOE[o]); aOE[o]=fmaf(wp[5],v11,aOE[o]);
                aOO[o]=fmaf(wp[4],v11,aOO[o]);
            }
        }
    }
    const int ye=y0o+2*ty, xe=x0o+2*tx;
#pragma unroll
    for (int o=0;o<8;o++){
        float bv=bias[ocb+o];
        float vEE=aEE[o]+bv,vEO=aEO[o]+bv,vOE=aOE[o]+bv,vOO=aOO[o]+bv;
        if (flags&1){ vEE=(vEE>=0.f)?vEE:0.1f*vEE; vEO=(vEO>=0.f)?vEO:0.1f*vEO;
                      vOE=(vOE>=0.f)?vOE:0.1f*vOE; vOO=(vOO>=0.f)?vOO:0.1f*vOO; }
        size_t base=((size_t)(n*NF+ocb+o)*Hout+ye)*Hout+xe;
        out[base]=vEE; out[base+1]=vEO; out[base+Hout]=vOE; out[base+Hout+1]=vOO;
    }
}

// ---------------- DCN sampling ------------------------------------------------
__global__ __launch_bounds__(256) void dcn_sample(
    const float* __restrict__ ref, const float* __restrict__ off,
    float* __restrict__ S)
{
    int idx=blockIdx.x*256+threadIdx.x;
    if (idx>=BN*GD*K2T*HWSZ) return;
    int p=idx&(HWSZ-1); int t=idx>>14;
    int k=t%9; t/=9; int g=t%GD, n=t/GD;
    int y=p>>7, x=p&127;
    int offc=(g*9+k)*2;
    float dy=off[((size_t)(n*2*GD*K2T+offc))*HWSZ+p];
    float dx=off[((size_t)(n*2*GD*K2T+offc+1))*HWSZ+p];
    float py=(float)y+(float)(k/3-1)+dy;
    float px=(float)x+(float)(k%3-1)+dx;
    float fy=floorf(py), fx=floorf(px);
    float wy=py-fy, wx=px-fx;
    int iy=(int)fy, ix=(int)fx;
    float wgt[4]; int ofs[4];
#pragma unroll
    for (int r=0;r<2;r++)
#pragma unroll
        for (int c=0;c<2;c++){
            int yy=iy+r, xx=ix+c;
            bool val=((unsigned)yy<(unsigned)HH)&&((unsigned)xx<(unsigned)WW);
            float wv=(r?wy:1.f-wy)*(c?wx:1.f-wx);
            wgt[r*2+c]=val?wv:0.f; ofs[r*2+c]=val?(yy*WW+xx):0;
        }
    const float* base=ref+(size_t)(n*NF+g*8)*HWSZ;
    float* so=S+((size_t)(n*NF+g*8)*9+k)*HWSZ+p;
#pragma unroll
    for (int c=0;c<8;c++){
        const float* bp=base+(size_t)c*HWSZ;
        so[(size_t)c*9*HWSZ]=wgt[0]*bp[ofs[0]]+wgt[1]*bp[ofs[1]]+wgt[2]*bp[ofs[2]]+wgt[3]*bp[ofs[3]];
    }
}

// ================= mma.sync bf16 split-3 implicit GEMM (round-7 proven) ======
__device__ __forceinline__ void split2(float v0, float v1, uint32_t& hi, uint32_t& lo){
    __nv_bfloat16 h0=__float2bfloat16(v0), h1=__float2bfloat16(v1);
    __nv_bfloat16 l0=__float2bfloat16(v0-__bfloat162float(h0));
    __nv_bfloat16 l1=__float2bfloat16(v1-__bfloat162float(h1));
    hi=((uint32_t)__bfloat16_as_ushort(h1)<<16)|__bfloat16_as_ushort(h0);
    lo=((uint32_t)__bfloat16_as_ushort(l1)<<16)|__bfloat16_as_ushort(l0);
}
#define MMA4(d,a0,a1,a2,a3,b0,b1) \
    asm volatile("mma.sync.aligned.m16n8k16.row.col.f32.bf16.bf16.f32 " \
        "{%0,%1,%2,%3},{%4,%5,%6,%7},{%8,%9},{%0,%1,%2,%3};" \
        : "+f"(d[0]),"+f"(d[1]),"+f"(d[2]),"+f"(d[3]) \
        : "r"(a0),"r"(a1),"r"(a2),"r"(a3),"r"(b0),"r"(b1))

template<int NF8, int MODE>
__global__ __launch_bounds__(256, 2) void gemm_tc(
    const float* __restrict__ inA, int cinA,
    const float* __restrict__ inB, int cinB,
    const float* __restrict__ w, const float* __restrict__ bias,
    float* __restrict__ out, int cout, int flags)
{
    extern __shared__ uint32_t sm[];
    const int Ncta = NF8*16;
    const int AW = 128*18, BW = Ncta*18, PB = 2*AW + 2*BW;
    const int tid=threadIdx.x, lane=tid&31, wid=tid>>5;
    const int g=lane>>2, tig=lane&3;
    const int y=blockIdx.x, n=blockIdx.z;
    const int ocb = blockIdx.y * Ncta;
    const int cin = cinA + cinB;
    const int K = MODE ? cin : cin*9;
    const int nch = K/32;
    const int mIdx = (wid&3)*32, nIdx = (wid>>2)*NF8*8;
    const int apx = tid & 127, ah_ = tid >> 7;

    uint32_t pah[8], pal[8], pbh[NF8], pbl[NF8];

#define FETCH_A(kk, dst) { float vv=0.f; int k_=(kk); \
    if (MODE){ vv = __ldg(inA + ((size_t)(n*cin + k_))*HWSZ + y*WW + apx); } \
    else { int ic_=k_/9, tp_=k_-ic_*9; int gy=y-1+tp_/3, gx=apx-1+tp_%3; \
        if ((unsigned)gy<(unsigned)HH && (unsigned)gx<(unsigned)WW){ \
            const float* p_=(ic_<cinA)? inA+((size_t)(n*cinA+ic_)*HH+gy)*WW+gx \
                                      : inB+((size_t)(n*cinB+(ic_-cinA))*HH+gy)*WW+gx; \
            vv=__ldg(p_); } } \
    dst=vv; }

#define G_LOAD(C) { const int c_=(C); \
    _Pragma("unroll") for (int i=0;i<8;i++){ \
        int k0 = c_*32 + (ah_*8+i)*2; \
        float v0, v1; FETCH_A(k0, v0); FETCH_A(k0+1, v1); \
        split2(v0, v1, pah[i], pal[i]); } \
    _Pragma("unroll") for (int j=0;j<NF8;j++){ \
        int idx = tid + 256*j; int oc = idx>>4, kp = idx&15; \
        int k0 = c_*32 + kp*2; int ocg = ocb + oc; \
        float v0=0.f, v1=0.f; \
        if (ocg < cout){ \
            if (MODE){ v0=__ldg(w+(size_t)ocg*cin+k0); v1=__ldg(w+(size_t)ocg*cin+k0+1); } \
            else { int ic0_=k0/9, t0_=k0-ic0_*9; v0=__ldg(w+((size_t)ocg*cin+ic0_)*9+t0_); \
                   int k1=k0+1; int ic1_=k1/9, t1_=k1-ic1_*9; v1=__ldg(w+((size_t)ocg*cin+ic1_)*9+t1_); } } \
        split2(v0, v1, pbh[j], pbl[j]); } }

#define G_STORE(B) { uint32_t* bb = sm + (B)*PB; \
    _Pragma("unroll") for (int i=0;i<8;i++){ \
        int word = apx*18 + ah_*8 + i; \
        bb[word] = pah[i]; bb[AW + word] = pal[i]; } \
    _Pragma("unroll") for (int j=0;j<NF8;j++){ \
        int idx = tid + 256*j; int oc = idx>>4, kp = idx&15; \
        int word = oc*18 + kp; \
        bb[2*AW + word] = pbh[j]; bb[2*AW + BW + word] = pbl[j]; } }

    float acc[2][NF8][4];
#pragma unroll
    for (int mt=0;mt<2;mt++)
#pragma unroll
        for (int j=0;j<NF8;j++)
#pragma unroll
            for (int q=0;q<4;q++) acc[mt][j][q]=0.f;

    G_LOAD(0); G_STORE(0); __syncthreads();

    for (int c=0;c<nch;c++){
        const int b=c&1;
        if (c+1<nch) G_LOAD(c+1);
        const uint32_t* Ah = sm + b*PB;
        const uint32_t* Al = Ah + AW;
        const uint32_t* Bh = Ah + 2*AW;
        const uint32_t* Bl = Bh + BW;
#pragma unroll
        for (int ks=0;ks<2;ks++){
            uint32_t ha[2][4], la[2][4];
#pragma unroll
            for (int mt=0;mt<2;mt++){
                int r = mIdx + mt*16 + g;
                int w0 = r*18 + ks*8 + tig;
                ha[mt][0]=Ah[w0];        ha[mt][1]=Ah[w0+8*18];
                ha[mt][2]=Ah[w0+4];      ha[mt][3]=Ah[w0+8*18+4];
                la[mt][0]=Al[w0];        la[mt][1]=Al[w0+8*18];
                la[mt][2]=Al[w0+4];      la[mt][3]=Al[w0+8*18+4];
            }
#pragma unroll
            for (int j=0;j<NF8;j++){
                int cc = nIdx + j*8 + g;
                int w0 = cc*18 + ks*8 + tig;
                uint32_t bh0=Bh[w0], bh1=Bh[w0+4];
                uint32_t bl0=Bl[w0], bl1=Bl[w0+4];
#pragma unroll
                for (int mt=0;mt<2;mt++){
                    MMA4(acc[mt][j], ha[mt][0],ha[mt][1],ha[mt][2],ha[mt][3], bh0,bh1);
                    MMA4(acc[mt][j], la[mt][0],la[mt][1],la[mt][2],la[mt][3], bh0,bh1);
                    MMA4(acc[mt][j], ha[mt][0],ha[mt][1],ha[mt][2],ha[mt][3], bl0,bl1);
                }
            }
        }
        if (c+1<nch){ G_STORE((c+1)&1); __syncthreads(); }
    }

    // epilogue: d0:(px,oc0) d1:(px,oc0+1) d2:(px+8,oc0) d3:(px+8,oc0+1)
#pragma unroll
    for (int mt=0;mt<2;mt++){
        int px0 = mIdx + mt*16 + g;
#pragma unroll
        for (int j=0;j<NF8;j++){
            int oc0 = ocb + nIdx + j*8 + 2*tig;
#pragma unroll
            for (int q=0;q<4;q++){
                int oc = oc0 + (q&1);
                int px = px0 + ((q>>1)*8);
                if (oc < cout){
                    float v = acc[mt][j][q] + bias[oc];
                    if (flags&1) v=(v>=0.f)?v:0.1f*v;
                    float* op = out + ((size_t)(n*cout+oc)*HH + y)*WW + px;
                    if (flags&2) *op += v; else *op = v;
                }
            }
        }
    }
#undef FETCH_A
#undef G_LOAD
#undef G_STORE
}

// ------------------------------ launch ---------------------------------------
extern "C" void kernel_launch(void* const* d_in, const int* in_sizes, int n_in,
                              void* d_out, int out_size)
{
    const float* ref   = (const float*)d_in[0];
    const float* inp   = (const float*)d_in[1];
    const float* w_oc1 = (const float*)d_in[2];  const float* b_oc1 = (const float*)d_in[3];
    const float* w_oc3 = (const float*)d_in[4];  const float* b_oc3 = (const float*)d_in[5];
    const float* w_e1  = (const float*)d_in[6];  const float* b_e1  = (const float*)d_in[7];
    const float* w_e2  = (const float*)d_in[8];  const float* b_e2  = (const float*)d_in[9];
    const float* w_d1  = (const float*)d_in[10]; const float* b_d1  = (const float*)d_in[11];
    const float* w_d2  = (const float*)d_in[12]; const float* b_d2  = (const float*)d_in[13];
    const float* w_off = (const float*)d_in[14]; const float* b_off = (const float*)d_in[15];
    const float* w_dcn = (const float*)d_in[16]; const float* b_dcn = (const float*)d_in[17];
    const float* w_c1  = (const float*)d_in[18]; const float* b_c1  = (const float*)d_in[19];
    const float* w_c2  = (const float*)d_in[20]; const float* b_c2  = (const float*)d_in[21];

    float* out  = (float*)d_out;
    float* oL1  = out;
    float* oEN  = out + (size_t)BN*NF*HWSZ;
    float* oQ   = oEN + (size_t)BN*NF*32*32;
    float* oDEC = oQ  + (size_t)BN*NF*32*32;

    float *t1, *t2, *e1b, *d1b, *offb, *Sb;
    cudaGetSymbolAddress((void**)&t1,   g_t1);
    cudaGetSymbolAddress((void**)&t2,   g_t2);
    cudaGetSymbolAddress((void**)&e1b,  g_e1);
    cudaGetSymbolAddress((void**)&d1b,  g_d1);
    cudaGetSymbolAddress((void**)&offb, g_off);
    cudaGetSymbolAddress((void**)&Sb,   g_S);

    const int smem7 = (2*(2*128*18 + 2*112*18))*4;   // 69120
    const int smem6 = (2*(2*128*18 + 2*96*18))*4;    // 64512
    cudaFuncSetAttribute(gemm_tc<7,0>, cudaFuncAttributeMaxDynamicSharedMemorySize, smem7);
    cudaFuncSetAttribute(gemm_tc<6,0>, cudaFuncAttributeMaxDynamicSharedMemorySize, smem6);
    cudaFuncSetAttribute(gemm_tc<6,1>, cudaFuncAttributeMaxDynamicSharedMemorySize, smem6);

    conv3x3_s1v2<<<dim3(16, 12, BN), 256>>>(ref, NF, inp, NF, w_oc1, b_oc1, t1, NF, 1);
    conv3x3_s1v2<<<dim3(16, 12, BN), 256>>>(t1, NF, nullptr, 0, w_oc3, b_oc3, t2, NF, 1);
    conv3x3_s2v2<<<dim3(16, 12, BN), 256>>>(t2, 128, w_e1, b_e1, e1b, nullptr, 1);
    conv3x3_s2v2<<<dim3(4,  12, BN), 256>>>(e1b, 64, w_e2, b_e2, oEN, oQ, 0);
    deconv3x3_x2<<<dim3(4,  12, BN), 256>>>(oQ,  32, w_d1, b_d1, d1b, 1);
    deconv3x3_x2<<<dim3(16, 12, BN), 256>>>(d1b, 64, w_d2, b_d2, oDEC, 0);
    // offset head (216 ch): 2 oc-blocks of 112
    gemm_tc<7,0><<<dim3(128, 2, BN), 256, smem7>>>(oDEC, NF, nullptr, 0, w_off, b_off, offb, 216, 0);
    dcn_sample<<<(BN*GD*K2T*HWSZ)/256, 256>>>(ref, offb, Sb);
    // DCN 1x1 GEMM over 864 channels
    gemm_tc<6,1><<<dim3(128, 1, BN), 256, smem6>>>(Sb, NF*K2T, nullptr, 0, w_dcn, b_dcn, oL1, NF, 0);
    // fusion tail
    gemm_tc<6,0><<<dim3(128, 1, BN), 256, smem6>>>(oL1, NF, ref, NF, w_c1, b_c1, t1, NF, 1);
    gemm_tc<6,0><<<dim3(128, 1, BN), 256, smem6>>>(t1, NF, nullptr, 0, w_c2, b_c2, oL1, NF, 3);
}

// round 15
// speedup vs baseline: 1.2125x; 1.0198x over previous
#include <cuda_runtime.h>
#include <cuda_bf16.h>
#include <math.h>
#include <stdint.h>

#define NF 96
#define GD 12
#define K2T 9
#define BN 4
#define HH 128
#define WW 128
#define HWSZ (HH*WW)

__device__ float g_t1[BN*NF*HWSZ];
__device__ float g_t2[BN*NF*HWSZ];
__device__ float g_e1[BN*NF*64*64];
__device__ float g_d1[BN*NF*64*64];
__device__ float g_off[BN*2*GD*K2T*HWSZ];
__device__ float g_S[BN*NF*K2T*HWSZ];

// ======== fp32 3x3 s1 conv, full-row tile, 8px x 8oc per thread (oc1, oc3) ===
// CTA: 128 x 16 outputs, 8 oc. ic-chunk = 2, double-buffered, reg prefetch.
// Accumulation order (ic asc, dy, dx) identical to prior kernels -> bit-exact.
__global__ __launch_bounds__(256) void conv3x3_s1v3(
    const float* __restrict__ inA, int cinA,
    const float* __restrict__ inB, int cinB,
    const float* __restrict__ w, const float* __restrict__ bias,
    float* __restrict__ out, int cout, int flags)
{
    const int tid = threadIdx.x;
    const int tx = tid & 15;          // x-group of 8
    const int ty = tid >> 4;          // row 0..15
    const int y0 = blockIdx.x * 16;
    const int ocb = blockIdx.y * 8, n = blockIdx.z;
    const int cin = cinA + cinB, nch = cin >> 1;

    __shared__ float sIn[2][2][18][132];   // [buf][ic][row][col] col=gx+1, 528B rows
    __shared__ float sW[2][144];           // [buf][o*18 + ic*9 + tap]

    float rI[19]; float rw0;

#define V3_LOAD(IC0) { const int ic0_=(IC0); \
    _Pragma("unroll") for (int k=0;k<19;k++){ int idx=tid+256*k; \
      if (k<18||tid<72){ int ic=idx/2340; int rem=idx-ic*2340; int rr=rem/130; int cc=rem-rr*130; \
        int gy=y0-1+rr, gx=cc-1; bool inb=((unsigned)gy<(unsigned)HH)&&((unsigned)gx<(unsigned)WW); \
        int icg=ic0_+ic; const float* p=(icg<cinA)?(inA+((size_t)(n*cinA+icg)*HH+gy)*WW+gx):(inB+((size_t)(n*cinB+(icg-cinA))*HH+gy)*WW+gx); \
        rI[k]=inb?__ldg(p):0.f; } } \
    if (tid<144){ int o=tid/18, ic=(tid/9)%2, t=tid%9; \
        rw0=w[((size_t)(ocb+o)*cin+ic0_+ic)*9+t]; } }
#define V3_STORE(B) { float* sb=&sIn[B][0][0][0]; \
    _Pragma("unroll") for (int k=0;k<19;k++){ int idx=tid+256*k; \
      if (k<18||tid<72){ int ic=idx/2340; int rem=idx-ic*2340; int rr=rem/130; int cc=rem-rr*130; \
        sb[(ic*18+rr)*132+cc]=rI[k]; } } \
    if (tid<144) sW[B][tid]=rw0; }

    float acc[8][8];
#pragma unroll
    for (int o=0;o<8;o++)
#pragma unroll
      for (int j=0;j<8;j++) acc[o][j]=0.f;

    V3_LOAD(0); V3_STORE(0); __syncthreads();

    for (int c=0;c<nch;c++){
        const int b=c&1;
        if (c+1<nch) V3_LOAD((c+1)*2);
#pragma unroll
        for (int ic=0;ic<2;ic++){
#pragma unroll
            for (int dy=0;dy<3;dy++){
                const float* rp=&sIn[b][ic][ty+dy][8*tx];
                float4 va=*(const float4*)rp;
                float4 vb=*(const float4*)(rp+4);
                float2 vc=*(const float2*)(rp+8);
                float v[10]={va.x,va.y,va.z,va.w,vb.x,vb.y,vb.z,vb.w,vc.x,vc.y};
                const float* wrow=&sW[b][ic*9+dy*3];
#pragma unroll
                for (int dx=0;dx<3;dx++){
                    float wv[8];
#pragma unroll
                    for (int o=0;o<8;o++) wv[o]=wrow[o*18+dx];
#pragma unroll
                    for (int j=0;j<8;j++){ float xv=v[j+dx];
#pragma unroll
                        for (int o=0;o<8;o++) acc[o][j]=fmaf(wv[o],xv,acc[o][j]); }
                }
            }
        }
        if (c+1<nch){ V3_STORE((c+1)&1); __syncthreads(); }
    }

    const int y=y0+ty, xb=8*tx;
#pragma unroll
    for (int o=0;o<8;o++){
        float bv=bias[ocb+o];
        float vv[8];
#pragma unroll
        for (int j=0;j<8;j++){
            float v=acc[o][j]+bv;
            if (flags&1) v=(v>=0.f)?v:0.1f*v;
            vv[j]=v;
        }
        float* op=out+((size_t)(n*cout+ocb+o)*HH+y)*WW+xb;
        if (flags&2){
            float4 p0=*(float4*)op; float4 p1=*(float4*)(op+4);
            p0.x+=vv[0]; p0.y+=vv[1]; p0.z+=vv[2]; p0.w+=vv[3];
            p1.x+=vv[4]; p1.y+=vv[5]; p1.z+=vv[6]; p1.w+=vv[7];
            *(float4*)op=p0; *(float4*)(op+4)=p1;
        } else {
            *(float4*)op    =make_float4(vv[0],vv[1],vv[2],vv[3]);
            *(float4*)(op+4)=make_float4(vv[4],vv[5],vv[6],vv[7]);
        }
    }
#undef V3_LOAD
#undef V3_STORE
}

// ---------------- fp32 pipelined 3x3 s2 conv (e1, e2) ------------------------
__global__ __launch_bounds__(256) void conv3x3_s2v2(
    const float* __restrict__ in, int Hin,
    const float* __restrict__ w, const float* __restrict__ bias,
    float* __restrict__ out, float* __restrict__ out_q, int flags)
{
    const int tid=threadIdx.x, tx=tid&15, ty=tid>>4;
    const int Hout=Hin>>1, tilesX=Hout>>4;
    const int x0=(blockIdx.x%tilesX)*16, y0=(blockIdx.x/tilesX)*16;
    const int ocb=blockIdx.y*8, n=blockIdx.z;
    __shared__ float sIn[2][2][33][34];
    __shared__ float sW[2][8*2*9];
    float rI[9]; float rw0;
#define S2_LOAD(IC0) { const int ic0_=(IC0); \
    _Pragma("unroll") for (int k=0;k<9;k++){ int idx=tid+256*k; \
      if (k<8||tid<130){ int ic=idx/1089; int rem=idx-ic*1089; int rr=rem/33; int cc=rem-rr*33; \
        int gy=2*y0+rr, gx=2*x0+cc; bool inb=(gy<Hin)&&(gx<Hin); \
        rI[k]=inb?__ldg(in+((size_t)(n*NF+ic0_+ic)*Hin+gy)*Hin+gx):0.f; } } \
    if (tid<144){ int o=tid/18, ic=(tid/9)%2, t=tid%9; rw0=w[((size_t)(ocb+o)*NF+ic0_+ic)*9+t]; } }
#define S2_STORE(B) { float* sb=&sIn[B][0][0][0]; \
    _Pragma("unroll") for (int k=0;k<9;k++){ int idx=tid+256*k; \
      if (k<8||tid<130){ int ic=idx/1089; int rem=idx-ic*1089; int rr=rem/33; int cc=rem-rr*33; \
        sb[(ic*33+rr)*34+cc]=rI[k]; } } \
    if (tid<144) sW[B][tid]=rw0; }
    float acc[8];
#pragma unroll
    for (int o=0;o<8;o++) acc[o]=0.f;
    S2_LOAD(0); S2_STORE(0); __syncthreads();
    const int nch=NF/2;
    for (int c=0;c<nch;c++){
        const int b=c&1;
        if (c+1<nch) S2_LOAD((c+1)*2);
#pragma unroll
        for (int ic=0;ic<2;ic++)
#pragma unroll
            for (int dy=0;dy<3;dy++)
#pragma unroll
                for (int dx=0;dx<3;dx++){
                    float xv=sIn[b][ic][2*ty+dy][2*tx+dx];
                    const float* wp=&sW[b][ic*9+dy*3+dx];
#pragma unroll
                    for (int o=0;o<8;o++) acc[o]=fmaf(wp[o*18],xv,acc[o]);
                }
        if (c+1<nch){ S2_STORE((c+1)&1); __syncthreads(); }
    }
#pragma unroll
    for (int o=0;o<8;o++){
        float v=acc[o]+bias[ocb+o];
        if (flags&1) v=(v>=0.f)?v:0.1f*v;
        size_t oi=((size_t)(n*NF+ocb+o)*Hout+(y0+ty))*Hout+(x0+tx);
        out[oi]=v;
        if (out_q) out_q[oi]=rintf(v);
    }
#undef S2_LOAD
#undef S2_STORE
}

// ---------------- fp32 transpose conv (d1, d2) --------------------------------
__global__ __launch_bounds__(256) void deconv3x3_x2(
    const float* __restrict__ in, int Hin,
    const float* __restrict__ w, const float* __restrict__ bias,
    float* __restrict__ out, int flags)
{
    const int tid=threadIdx.x, tx=tid&15, ty=tid>>4;
    const int Hout=Hin*2, tilesX=Hout>>5;
    const int tX=blockIdx.x%tilesX, tY=blockIdx.x/tilesX;
    const int xin0=tX*16, yin0=tY*16, x0o=tX*32, y0o=tY*32;
    const int ocb=blockIdx.y*8, n=blockIdx.z;
    __shared__ float sIn[4][17][18];
    __shared__ float sW[8][4][9];
    float aEE[8],aEO[8],aOE[8],aOO[8];
#pragma unroll
    for (int o=0;o<8;o++){aEE[o]=0.f;aEO[o]=0.f;aOE[o]=0.f;aOO[o]=0.f;}
    for (int ic0=0;ic0<NF;ic0+=4){
        __syncthreads();
        for (int idx=tid;idx<4*17*17;idx+=256){
            int ic=idx/(17*17), r=(idx/17)%17, c=idx%17;
            int gy=yin0-1+r, gx=xin0-1+c;
            float v=0.f;
            if ((unsigned)gy<(unsigned)Hin&&(unsigned)gx<(unsigned)Hin)
                v=in[((size_t)(n*NF+ic0+ic)*Hin+gy)*Hin+gx];
            sIn[ic][r][c]=v;
        }
        for (int idx=tid;idx<8*4*9;idx+=256){
            int o=idx/36, ic=(idx/9)%4, t=idx%9;
            sW[o][ic][t]=w[((size_t)(ocb+o)*NF+ic0+ic)*9+t];
        }
        __syncthreads();
#pragma unroll
        for (int ic=0;ic<4;ic++){
            float v00=sIn[ic][ty][tx], v01=sIn[ic][ty][tx+1];
            float v10=sIn[ic][ty+1][tx], v11=sIn[ic][ty+1][tx+1];
#pragma unroll
            for (int o=0;o<8;o++){
                const float* wp=&sW[o][ic][0];
                aEE[o]=fmaf(wp[0],v00,aEE[o]); aEE[o]=fmaf(wp[2],v01,aEE[o]);
                aEE[o]=fmaf(wp[6],v10,aEE[o]); aEE[o]=fmaf(wp[8],v11,aEE[o]);
                aEO[o]=fmaf(wp[1],v01,aEO[o]); aEO[o]=fmaf(wp[7],v11,aEO[o]);
                aOE[o]=fmaf(wp[3],v10,aOE[o]); aOE[o]=fmaf(wp[5],v11,aOE[o]);
                aOO[o]=fmaf(wp[4],v11,aOO[o]);
            }
        }
    }
    const int ye=y0o+2*ty, xe=x0o+2*tx;
#pragma unroll
    for (int o=0;o<8;o++){
        float bv=bias[ocb+o];
        float vEE=aEE[o]+bv,vEO=aEO[o]+bv,vOE=aOE[o]+bv,vOO=aOO[o]+bv;
        if (flags&1){ vEE=(vEE>=0.f)?vEE:0.1f*vEE; vEO=(vEO>=0.f)?vEO:0.1f*vEO;
                      vOE=(vOE>=0.f)?vOE:0.1f*vOE; vOO=(vOO>=0.f)?vOO:0.1f*vOO; }
        size_t base=((size_t)(n*NF+ocb+o)*Hout+ye)*Hout+xe;
        out[base]=vEE; out[base+1]=vEO; out[base+Hout]=vOE; out[base+Hout+1]=vOO;
    }
}

// ---------------- DCN sampling ------------------------------------------------
__global__ __launch_bounds__(256) void dcn_sample(
    const float* __restrict__ ref, const float* __restrict__ off,
    float* __restrict__ S)
{
    int idx=blockIdx.x*256+threadIdx.x;
    if (idx>=BN*GD*K2T*HWSZ) return;
    int p=idx&(HWSZ-1); int t=idx>>14;
    int k=t%9; t/=9; int g=t%GD, n=t/GD;
    int y=p>>7, x=p&127;
    int offc=(g*9+k)*2;
    float dy=off[((size_t)(n*2*GD*K2T+offc))*HWSZ+p];
    float dx=off[((size_t)(n*2*GD*K2T+offc+1))*HWSZ+p];
    float py=(float)y+(float)(k/3-1)+dy;
    float px=(float)x+(float)(k%3-1)+dx;
    float fy=floorf(py), fx=floorf(px);
    float wy=py-fy, wx=px-fx;
    int iy=(int)fy, ix=(int)fx;
    float wgt[4]; int ofs[4];
#pragma unroll
    for (int r=0;r<2;r++)
#pragma unroll
        for (int c=0;c<2;c++){
            int yy=iy+r, xx=ix+c;
            bool val=((unsigned)yy<(unsigned)HH)&&((unsigned)xx<(unsigned)WW);
            float wv=(r?wy:1.f-wy)*(c?wx:1.f-wx);
            wgt[r*2+c]=val?wv:0.f; ofs[r*2+c]=val?(yy*WW+xx):0;
        }
    const float* base=ref+(size_t)(n*NF+g*8)*HWSZ;
    float* so=S+((size_t)(n*NF+g*8)*9+k)*HWSZ+p;
#pragma unroll
    for (int c=0;c<8;c++){
        const float* bp=base+(size_t)c*HWSZ;
        so[(size_t)c*9*HWSZ]=wgt[0]*bp[ofs[0]]+wgt[1]*bp[ofs[1]]+wgt[2]*bp[ofs[2]]+wgt[3]*bp[ofs[3]];
    }
}

// ================= mma.sync bf16 split-3 implicit GEMM (round-14 winner) =====
__device__ __forceinline__ void split2(float v0, float v1, uint32_t& hi, uint32_t& lo){
    __nv_bfloat16 h0=__float2bfloat16(v0), h1=__float2bfloat16(v1);
    __nv_bfloat16 l0=__float2bfloat16(v0-__bfloat162float(h0));
    __nv_bfloat16 l1=__float2bfloat16(v1-__bfloat162float(h1));
    hi=((uint32_t)__bfloat16_as_ushort(h1)<<16)|__bfloat16_as_ushort(h0);
    lo=((uint32_t)__bfloat16_as_ushort(l1)<<16)|__bfloat16_as_ushort(l0);
}
#define MMA4(d,a0,a1,a2,a3,b0,b1) \
    asm volatile("mma.sync.aligned.m16n8k16.row.col.f32.bf16.bf16.f32 " \
        "{%0,%1,%2,%3},{%4,%5,%6,%7},{%8,%9},{%0,%1,%2,%3};" \
        : "+f"(d[0]),"+f"(d[1]),"+f"(d[2]),"+f"(d[3]) \
        : "r"(a0),"r"(a1),"r"(a2),"r"(a3),"r"(b0),"r"(b1))

template<int NF8, int MODE>
__global__ __launch_bounds__(256, 2) void gemm_tc(
    const float* __restrict__ inA, int cinA,
    const float* __restrict__ inB, int cinB,
    const float* __restrict__ w, const float* __restrict__ bias,
    float* __restrict__ out, int cout, int flags)
{
    extern __shared__ uint32_t sm[];
    const int Ncta = NF8*16;
    const int AW = 128*18, BW = Ncta*18, PB = 2*AW + 2*BW;
    const int tid=threadIdx.x, lane=tid&31, wid=tid>>5;
    const int g=lane>>2, tig=lane&3;
    const int y=blockIdx.x, n=blockIdx.z;
    const int ocb = blockIdx.y * Ncta;
    const int cin = cinA + cinB;
    const int K = MODE ? cin : cin*9;
    const int nch = K/32;
    const int mIdx = (wid&3)*32, nIdx = (wid>>2)*NF8*8;
    const int apx = tid & 127, ah_ = tid >> 7;

    uint32_t pah[8], pal[8], pbh[NF8], pbl[NF8];

#define FETCH_A(kk, dst) { float vv=0.f; int k_=(kk); \
    if (MODE){ vv = __ldg(inA + ((size_t)(n*cin + k_))*HWSZ + y*WW + apx); } \
    else { int ic_=k_/9, tp_=k_-ic_*9; int gy=y-1+tp_/3, gx=apx-1+tp_%3; \
        if ((unsigned)gy<(unsigned)HH && (unsigned)gx<(unsigned)WW){ \
            const float* p_=(ic_<cinA)? inA+((size_t)(n*cinA+ic_)*HH+gy)*WW+gx \
                                      : inB+((size_t)(n*cinB+(ic_-cinA))*HH+gy)*WW+gx; \
            vv=__ldg(p_); } } \
    dst=vv; }

#define G_LOAD(C) { const int c_=(C); \
    _Pragma("unroll") for (int i=0;i<8;i++){ \
        int k0 = c_*32 + (ah_*8+i)*2; \
        float v0, v1; FETCH_A(k0, v0); FETCH_A(k0+1, v1); \
        split2(v0, v1, pah[i], pal[i]); } \
    _Pragma("unroll") for (int j=0;j<NF8;j++){ \
        int idx = tid + 256*j; int oc = idx>>4, kp = idx&15; \
        int k0 = c_*32 + kp*2; int ocg = ocb + oc; \
        float v0=0.f, v1=0.f; \
        if (ocg < cout){ \
            if (MODE){ v0=__ldg(w+(size_t)ocg*cin+k0); v1=__ldg(w+(size_t)ocg*cin+k0+1); } \
            else { int ic0_=k0/9, t0_=k0-ic0_*9; v0=__ldg(w+((size_t)ocg*cin+ic0_)*9+t0_); \
                   int k1=k0+1; int ic1_=k1/9, t1_=k1-ic1_*9; v1=__ldg(w+((size_t)ocg*cin+ic1_)*9+t1_); } } \
        split2(v0, v1, pbh[j], pbl[j]); } }

#define G_STORE(B) { uint32_t* bb = sm + (B)*PB; \
    _Pragma("unroll") for (int i=0;i<8;i++){ \
        int word = apx*18 + ah_*8 + i; \
        bb[word] = pah[i]; bb[AW + word] = pal[i]; } \
    _Pragma("unroll") for (int j=0;j<NF8;j++){ \
        int idx = tid + 256*j; int oc = idx>>4, kp = idx&15; \
        int word = oc*18 + kp; \
        bb[2*AW + word] = pbh[j]; bb[2*AW + BW + word] = pbl[j]; } }

    float acc[2][NF8][4];
#pragma unroll
    for (int mt=0;mt<2;mt++)
#pragma unroll
        for (int j=0;j<NF8;j++)
#pragma unroll
            for (int q=0;q<4;q++) acc[mt][j][q]=0.f;

    G_LOAD(0); G_STORE(0); __syncthreads();

    for (int c=0;c<nch;c++){
        const int b=c&1;
        if (c+1<nch) G_LOAD(c+1);
        const uint32_t* Ah = sm + b*PB;
        const uint32_t* Al = Ah + AW;
        const uint32_t* Bh = Ah + 2*AW;
        const uint32_t* Bl = Bh + BW;
#pragma unroll
        for (int ks=0;ks<2;ks++){
            uint32_t ha[2][4], la[2][4];
#pragma unroll
            for (int mt=0;mt<2;mt++){
                int r = mIdx + mt*16 + g;
                int w0 = r*18 + ks*8 + tig;
                ha[mt][0]=Ah[w0];        ha[mt][1]=Ah[w0+8*18];
                ha[mt][2]=Ah[w0+4];      ha[mt][3]=Ah[w0+8*18+4];
                la[mt][0]=Al[w0];        la[mt][1]=Al[w0+8*18];
                la[mt][2]=Al[w0+4];      la[mt][3]=Al[w0+8*18+4];
            }
#pragma unroll
            for (int j=0;j<NF8;j++){
                int cc = nIdx + j*8 + g;
                int w0 = cc*18 + ks*8 + tig;
                uint32_t bh0=Bh[w0], bh1=Bh[w0+4];
                uint32_t bl0=Bl[w0], bl1=Bl[w0+4];
#pragma unroll
                for (int mt=0;mt<2;mt++){
                    MMA4(acc[mt][j], ha[mt][0],ha[mt][1],ha[mt][2],ha[mt][3], bh0,bh1);
                    MMA4(acc[mt][j], la[mt][0],la[mt][1],la[mt][2],la[mt][3], bh0,bh1);
                    MMA4(acc[mt][j], ha[mt][0],ha[mt][1],ha[mt][2],ha[mt][3], bl0,bl1);
                }
            }
        }
        if (c+1<nch){ G_STORE((c+1)&1); __syncthreads(); }
    }

    // epilogue: d0:(px,oc0) d1:(px,oc0+1) d2:(px+8,oc0) d3:(px+8,oc0+1)
#pragma unroll
    for (int mt=0;mt<2;mt++){
        int px0 = mIdx + mt*16 + g;
#pragma unroll
        for (int j=0;j<NF8;j++){
            int oc0 = ocb + nIdx + j*8 + 2*tig;
#pragma unroll
            for (int q=0;q<4;q++){
                int oc = oc0 + (q&1);
                int px = px0 + ((q>>1)*8);
                if (oc < cout){
                    float v = acc[mt][j][q] + bias[oc];
                    if (flags&1) v=(v>=0.f)?v:0.1f*v;
                    float* op = out + ((size_t)(n*cout+oc)*HH + y)*WW + px;
                    if (flags&2) *op += v; else *op = v;
                }
            }
        }
    }
#undef FETCH_A
#undef G_LOAD
#undef G_STORE
}

// ------------------------------ launch ---------------------------------------
extern "C" void kernel_launch(void* const* d_in, const int* in_sizes, int n_in,
                              void* d_out, int out_size)
{
    const float* ref   = (const float*)d_in[0];
    const float* inp   = (const float*)d_in[1];
    const float* w_oc1 = (const float*)d_in[2];  const float* b_oc1 = (const float*)d_in[3];
    const float* w_oc3 = (const float*)d_in[4];  const float* b_oc3 = (const float*)d_in[5];
    const float* w_e1  = (const float*)d_in[6];  const float* b_e1  = (const float*)d_in[7];
    const float* w_e2  = (const float*)d_in[8];  const float* b_e2  = (const float*)d_in[9];
    const float* w_d1  = (const float*)d_in[10]; const float* b_d1  = (const float*)d_in[11];
    const float* w_d2  = (const float*)d_in[12]; const float* b_d2  = (const float*)d_in[13];
    const float* w_off = (const float*)d_in[14]; const float* b_off = (const float*)d_in[15];
    const float* w_dcn = (const float*)d_in[16]; const float* b_dcn = (const float*)d_in[17];
    const float* w_c1  = (const float*)d_in[18]; const float* b_c1  = (const float*)d_in[19];
    const float* w_c2  = (const float*)d_in[20]; const float* b_c2  = (const float*)d_in[21];

    float* out  = (float*)d_out;
    float* oL1  = out;
    float* oEN  = out + (size_t)BN*NF*HWSZ;
    float* oQ   = oEN + (size_t)BN*NF*32*32;
    float* oDEC = oQ  + (size_t)BN*NF*32*32;

    float *t1, *t2, *e1b, *d1b, *offb, *Sb;
    cudaGetSymbolAddress((void**)&t1,   g_t1);
    cudaGetSymbolAddress((void**)&t2,   g_t2);
    cudaGetSymbolAddress((void**)&e1b,  g_e1);
    cudaGetSymbolAddress((void**)&d1b,  g_d1);
    cudaGetSymbolAddress((void**)&offb, g_off);
    cudaGetSymbolAddress((void**)&Sb,   g_S);

    const int smem7 = (2*(2*128*18 + 2*112*18))*4;   // 69120
    const int smem6 = (2*(2*128*18 + 2*96*18))*4;    // 64512
    cudaFuncSetAttribute(gemm_tc<7,0>, cudaFuncAttributeMaxDynamicSharedMemorySize, smem7);
    cudaFuncSetAttribute(gemm_tc<6,0>, cudaFuncAttributeMaxDynamicSharedMemorySize, smem6);
    cudaFuncSetAttribute(gemm_tc<6,1>, cudaFuncAttributeMaxDynamicSharedMemorySize, smem6);

    // oc1/oc3: wide-ILP fp32 (bit-identical accumulation order; quantizer-safe)
    conv3x3_s1v3<<<dim3(8, 12, BN), 256>>>(ref, NF, inp, NF, w_oc1, b_oc1, t1, NF, 1);
    conv3x3_s1v3<<<dim3(8, 12, BN), 256>>>(t1, NF, nullptr, 0, w_oc3, b_oc3, t2, NF, 1);
    conv3x3_s2v2<<<dim3(16, 12, BN), 256>>>(t2, 128, w_e1, b_e1, e1b, nullptr, 1);
    conv3x3_s2v2<<<dim3(4,  12, BN), 256>>>(e1b, 64, w_e2, b_e2, oEN, oQ, 0);
    deconv3x3_x2<<<dim3(4,  12, BN), 256>>>(oQ,  32, w_d1, b_d1, d1b, 1);
    deconv3x3_x2<<<dim3(16, 12, BN), 256>>>(d1b, 64, w_d2, b_d2, oDEC, 0);
    // offset head (216 ch): 2 oc-blocks of 112
    gemm_tc<7,0><<<dim3(128, 2, BN), 256, smem7>>>(oDEC, NF, nullptr, 0, w_off, b_off, offb, 216, 0);
    dcn_sample<<<(BN*GD*K2T*HWSZ)/256, 256>>>(ref, offb, Sb);
    // DCN 1x1 GEMM over 864 channels
    gemm_tc<6,1><<<dim3(128, 1, BN), 256, smem6>>>(Sb, NF*K2T, nullptr, 0, w_dcn, b_dcn, oL1, NF, 0);
    // fusion tail
    gemm_tc<6,0><<<dim3(128, 1, BN), 256, smem6>>>(oL1, NF, ref, NF, w_c1, b_c1, t1, NF, 1);
    gemm_tc<6,0><<<dim3(128, 1, BN), 256, smem6>>>(t1, NF, nullptr, 0, w_c2, b_c2, oL1, NF, 3);
}